// round 14
// baseline (speedup 1.0000x reference)
#include <cuda_runtime.h>
#include <cuda_bf16.h>
#include <cstdint>
#include <math.h>

typedef __nv_bfloat16 bf16;

#define NSEQ 256
#define CZ   128
#define NHEAD 4
#define CHEAD 32
#define NROWS (NSEQ*NSEQ)   // 65536
#define LOG2E 1.4426950408889634f

#define CP_ASYNC16(dst, src) \
    asm volatile("cp.async.ca.shared.global [%0], [%1], 16;" :: "r"(dst), "l"(src))
#define CP_COMMIT() asm volatile("cp.async.commit_group;")
#define CP_WAIT(n)  asm volatile("cp.async.wait_group %0;" :: "n"(n))

__device__ __forceinline__ uint32_t smaddr(const void* p) {
    return (uint32_t)__cvta_generic_to_shared(p);
}
__device__ __forceinline__ float ex2(float x) {
    float r; asm("ex2.approx.ftz.f32 %0, %1;" : "=f"(r) : "f"(x)); return r;
}

// ---------------- scratch (static __device__, no allocation) ----------------
__device__ bf16  g_zn_h[(size_t)NROWS * CZ];
__device__ bf16  g_zn_l[(size_t)NROWS * CZ];
__device__ bf16  g_qkvh[(size_t)NROWS * 3 * CZ];
__device__ bf16  g_qkvl[(size_t)NROWS * 3 * CZ];
__device__ float g_gate[(size_t)NROWS * CZ];
__device__ float g_bias[(size_t)NHEAD * NROWS];     // [h][j*256+k], pre-scaled by log2e
__device__ bf16  g_go_h[(size_t)NROWS * CZ];
__device__ bf16  g_go_l[(size_t)NROWS * CZ];
__device__ bf16 g_wcat_h[128 * 512], g_wcat_l[128 * 512];
__device__ bf16 g_wo_h  [128 * 128], g_wo_l  [128 * 128];

// ---------------- LayerNorm + bf16 split + fused pair-bias (x log2e) --------
__global__ __launch_bounds__(256) void ln_kernel(const float* __restrict__ z,
                                                 const float* __restrict__ gam,
                                                 const float* __restrict__ bet,
                                                 const float* __restrict__ Wb)
{
    int row  = (blockIdx.x * blockDim.x + threadIdx.x) >> 5;
    int lane = threadIdx.x & 31;
    float4 v = *(const float4*)(z + (size_t)row * CZ + lane * 4);
    float s  = v.x + v.y + v.z + v.w;
    float ss = v.x*v.x + v.y*v.y + v.z*v.z + v.w*v.w;
    #pragma unroll
    for (int m = 16; m; m >>= 1) {
        s  += __shfl_xor_sync(0xffffffffu, s,  m);
        ss += __shfl_xor_sync(0xffffffffu, ss, m);
    }
    float mu   = s * (1.0f / CZ);
    float var  = ss * (1.0f / CZ) - mu * mu;
    float rstd = rsqrtf(var + 1e-5f);
    float4 gg = *(const float4*)(gam + lane * 4);
    float4 bb = *(const float4*)(bet + lane * 4);
    float o[4];
    o[0] = (v.x - mu) * rstd * gg.x + bb.x;
    o[1] = (v.y - mu) * rstd * gg.y + bb.y;
    o[2] = (v.z - mu) * rstd * gg.z + bb.z;
    o[3] = (v.w - mu) * rstd * gg.w + bb.w;
    bf16 h[4], l[4];
    #pragma unroll
    for (int t = 0; t < 4; ++t) {
        h[t] = __float2bfloat16(o[t]);
        l[t] = __float2bfloat16(o[t] - __bfloat162float(h[t]));
    }
    *(uint2*)(g_zn_h + (size_t)row * CZ + lane * 4) = *(uint2*)h;
    *(uint2*)(g_zn_l + (size_t)row * CZ + lane * 4) = *(uint2*)l;

    const float4* W4 = (const float4*)Wb;
    float4 acc = make_float4(0.f, 0.f, 0.f, 0.f);
    #pragma unroll
    for (int t = 0; t < 4; ++t) {
        float4 w = W4[lane * 4 + t];
        acc.x += o[t] * w.x; acc.y += o[t] * w.y;
        acc.z += o[t] * w.z; acc.w += o[t] * w.w;
    }
    #pragma unroll
    for (int m = 16; m; m >>= 1) {
        acc.x += __shfl_xor_sync(0xffffffffu, acc.x, m);
        acc.y += __shfl_xor_sync(0xffffffffu, acc.y, m);
        acc.z += __shfl_xor_sync(0xffffffffu, acc.z, m);
        acc.w += __shfl_xor_sync(0xffffffffu, acc.w, m);
    }
    if (lane == 0) {
        g_bias[(size_t)0 * NROWS + row] = acc.x * LOG2E;
        g_bias[(size_t)1 * NROWS + row] = acc.y * LOG2E;
        g_bias[(size_t)2 * NROWS + row] = acc.z * LOG2E;
        g_bias[(size_t)3 * NROWS + row] = acc.w * LOG2E;
    }
}

// ---------------- split weights into hi/lo bf16 (combined layout) ----------
__global__ __launch_bounds__(256) void cvt_w(const float* __restrict__ Wqkv,
                                             const float* __restrict__ Wg,
                                             const float* __restrict__ Wo)
{
    int i = blockIdx.x * 256 + threadIdx.x;   // 0..81919
    float x;
    bf16 *H, *L;
    int off;
    if (i < 65536) {
        int r = i >> 9, c = i & 511;
        x = (c < 384) ? Wqkv[r * 384 + c] : Wg[r * 128 + (c - 384)];
        H = g_wcat_h; L = g_wcat_l; off = i;
    } else {
        off = i - 65536;
        x = Wo[off];
        H = g_wo_h; L = g_wo_l;
    }
    bf16 h = __float2bfloat16(x);
    H[off] = h;
    L[off] = __float2bfloat16(x - __bfloat162float(h));
}

// ---------------- tensor-core GEMM, 2-stage cp.async pipeline ----------------
#define AS_STR 40
#define GSTG   20480                    // bf16 per stage (4 arrays x 128*40)
#define OFF_ASL 5120
#define OFF_BSH 10240
#define OFF_BSL 15360
#define GEMM_SMEM (2 * GSTG * 2)        // 80 KB

#define MMA16816(d, a, b0v, b1v)                                             \
  asm volatile("mma.sync.aligned.m16n8k16.row.col.f32.bf16.bf16.f32 "        \
    "{%0,%1,%2,%3}, {%4,%5,%6,%7}, {%8,%9}, {%0,%1,%2,%3};"                  \
    : "+f"(d[0]), "+f"(d[1]), "+f"(d[2]), "+f"(d[3])                         \
    : "r"(a[0]), "r"(a[1]), "r"(a[2]), "r"(a[3]), "r"(b0v), "r"(b1v))

#define GEMM_STAGE_A(kc, s)                                                  \
  { _Pragma("unroll")                                                        \
    for (int it = 0; it < 2; ++it) {                                         \
        int row = (tid >> 2) + it * 64, kq = tid & 3;                        \
        size_t so = (size_t)(m0 + row) * 128 + (kc) * 32 + kq * 8;           \
        uint32_t d = smaddr(gsm + (s) * GSTG + row * AS_STR + kq * 8);       \
        CP_ASYNC16(d, Ah + so);                                              \
        CP_ASYNC16(d + OFF_ASL * 2, Al + so);                                \
    } }

#define GEMM_LDB(kc)                                                         \
  { _Pragma("unroll")                                                        \
    for (int it = 0; it < 2; ++it) {                                         \
        int k = (tid >> 4) + it * 16, nq = tid & 15;                         \
        size_t so = (size_t)((kc) * 32 + k) * Nw + n0 + nq * 8;              \
        pbh[it] = *(const uint4*)(Bh + so);                                  \
        pbl[it] = *(const uint4*)(Bl + so);                                  \
    } }

#define GEMM_STB(s)                                                          \
  { _Pragma("unroll")                                                        \
    for (int it = 0; it < 2; ++it) {                                         \
        int k = (tid >> 4) + it * 16, nq = tid & 15;                         \
        int sw = k ^ (2 * nq);                                               \
        bf16 th[8], tl[8];                                                   \
        *(uint4*)th = pbh[it]; *(uint4*)tl = pbl[it];                        \
        bf16* dh = gsm + (s) * GSTG + OFF_BSH;                               \
        bf16* dl = gsm + (s) * GSTG + OFF_BSL;                               \
        _Pragma("unroll")                                                    \
        for (int e = 0; e < 8; ++e) {                                        \
            dh[(nq * 8 + e) * AS_STR + sw] = th[e];                          \
            dl[(nq * 8 + e) * AS_STR + sw] = tl[e];                          \
        }                                                                    \
    } }

// mode 0: f32 out (stride Nw)
// mode 3: combined qkv|gate: n<384 -> split bf16 (stride 384); n>=384 -> sigmoid f32 (stride 128)
__global__ __launch_bounds__(256) void mma_gemm(
    const bf16* __restrict__ Ah, const bf16* __restrict__ Al,
    const bf16* __restrict__ Bh, const bf16* __restrict__ Bl,
    float* __restrict__ C, bf16* __restrict__ Ch, bf16* __restrict__ Cl,
    int Nw, int mode)
{
    extern __shared__ bf16 gsm[];
    const int tid  = threadIdx.x;
    const int wid  = tid >> 5, lane = tid & 31;
    const int m0   = blockIdx.x * 128;
    const int n0   = blockIdx.y * 128;
    const int wm   = (wid & 3) * 32;
    const int wn   = (wid >> 2) * 64;
    const int lr   = lane >> 2;
    const int lc   = lane & 3;

    float acc[2][8][4];
    #pragma unroll
    for (int mt = 0; mt < 2; ++mt)
        #pragma unroll
        for (int nt = 0; nt < 8; ++nt)
            #pragma unroll
            for (int e = 0; e < 4; ++e) acc[mt][nt][e] = 0.0f;

    uint4 pbh[2], pbl[2];

    GEMM_STAGE_A(0, 0); CP_COMMIT();
    GEMM_LDB(0);
    GEMM_STB(0);

    int buf = 0;
    for (int kc = 0; kc < 4; ++kc) {
        if (kc < 3) {
            GEMM_STAGE_A(kc + 1, buf ^ 1); CP_COMMIT();
            GEMM_LDB(kc + 1);
            CP_WAIT(1);
        } else {
            CP_WAIT(0);
        }
        __syncthreads();

        const bf16* As_h = gsm + buf * GSTG;
        const bf16* As_l = As_h + OFF_ASL;
        const bf16* Bs_h = As_h + OFF_BSH;
        const bf16* Bs_l = As_h + OFF_BSL;

        #pragma unroll
        for (int kh = 0; kh < 2; ++kh) {
            const int kb = kh * 16;
            uint32_t afh[2][4], afl[2][4];
            #pragma unroll
            for (int mt = 0; mt < 2; ++mt) {
                int r = wm + mt * 16 + lr;
                int kcol = kb + lc * 2;
                afh[mt][0] = *(const uint32_t*)&As_h[ r      * AS_STR + kcol];
                afh[mt][1] = *(const uint32_t*)&As_h[(r + 8) * AS_STR + kcol];
                afh[mt][2] = *(const uint32_t*)&As_h[ r      * AS_STR + kcol + 8];
                afh[mt][3] = *(const uint32_t*)&As_h[(r + 8) * AS_STR + kcol + 8];
                afl[mt][0] = *(const uint32_t*)&As_l[ r      * AS_STR + kcol];
                afl[mt][1] = *(const uint32_t*)&As_l[(r + 8) * AS_STR + kcol];
                afl[mt][2] = *(const uint32_t*)&As_l[ r      * AS_STR + kcol + 8];
                afl[mt][3] = *(const uint32_t*)&As_l[(r + 8) * AS_STR + kcol + 8];
            }
            #pragma unroll
            for (int nt = 0; nt < 8; ++nt) {
                int n   = wn + nt * 8 + lr;
                int s   = 2 * ((n >> 3) & 15);
                int c0  = kb + lc * 2;
                uint32_t bh0 = *(const uint32_t*)&Bs_h[n * AS_STR + ( c0      ^ s)];
                uint32_t bh1 = *(const uint32_t*)&Bs_h[n * AS_STR + ((c0 + 8) ^ s)];
                uint32_t bl0 = *(const uint32_t*)&Bs_l[n * AS_STR + ( c0      ^ s)];
                uint32_t bl1 = *(const uint32_t*)&Bs_l[n * AS_STR + ((c0 + 8) ^ s)];
                #pragma unroll
                for (int mt = 0; mt < 2; ++mt) {
                    MMA16816(acc[mt][nt], afh[mt], bh0, bh1);
                    MMA16816(acc[mt][nt], afh[mt], bl0, bl1);
                    MMA16816(acc[mt][nt], afl[mt], bh0, bh1);
                }
            }
        }
        if (kc < 3) GEMM_STB(buf ^ 1);
        __syncthreads();
        buf ^= 1;
    }

    const int qkv_blk = (mode == 3) && (n0 < 384);
    const int gate_blk = (mode == 3) && (n0 >= 384);
    #pragma unroll
    for (int mt = 0; mt < 2; ++mt) {
        size_t r = (size_t)(m0 + wm + mt * 16 + lr);
        #pragma unroll
        for (int nt = 0; nt < 8; ++nt) {
            int n = n0 + wn + nt * 8 + lc * 2;
            float2 v0 = make_float2(acc[mt][nt][0], acc[mt][nt][1]);
            float2 v1 = make_float2(acc[mt][nt][2], acc[mt][nt][3]);
            if (qkv_blk) {
                __nv_bfloat162 h0 = __floats2bfloat162_rn(v0.x, v0.y);
                __nv_bfloat162 l0 = __floats2bfloat162_rn(v0.x - __bfloat162float(h0.x),
                                                          v0.y - __bfloat162float(h0.y));
                __nv_bfloat162 h1 = __floats2bfloat162_rn(v1.x, v1.y);
                __nv_bfloat162 l1 = __floats2bfloat162_rn(v1.x - __bfloat162float(h1.x),
                                                          v1.y - __bfloat162float(h1.y));
                *(__nv_bfloat162*)(Ch + r * 384 + n)       = h0;
                *(__nv_bfloat162*)(Cl + r * 384 + n)       = l0;
                *(__nv_bfloat162*)(Ch + (r + 8) * 384 + n) = h1;
                *(__nv_bfloat162*)(Cl + (r + 8) * 384 + n) = l1;
            } else if (gate_blk) {
                int c = n - 384;
                v0.x = 1.0f / (1.0f + ex2(-v0.x * LOG2E));
                v0.y = 1.0f / (1.0f + ex2(-v0.y * LOG2E));
                v1.x = 1.0f / (1.0f + ex2(-v1.x * LOG2E));
                v1.y = 1.0f / (1.0f + ex2(-v1.y * LOG2E));
                *(float2*)(C + r * 128 + c)       = v0;
                *(float2*)(C + (r + 8) * 128 + c) = v1;
            } else {
                *(float2*)(C + r * Nw + n)       = v0;
                *(float2*)(C + (r + 8) * Nw + n) = v1;
            }
        }
    }
}

// ---------------- tensor-core attention: 32 rows/warp, CTA = full (h,i) ----
// 256 thr = 8 warps x 32 j-rows = 256 rows. k in four 64-quarters, online softmax.
// Every K/V B-fragment load feeds 6 MMAs (2 m-tiles x 3 split terms).
#define QS_STR 40
#define KS_STR 40
#define VT_STR 264
#define ATTN_SMEM ((256*QS_STR + 256*KS_STR + 32*VT_STR) * 2 * 2)   // 113 KB

__global__ __launch_bounds__(256) void attn_kernel()
{
    extern __shared__ char smraw[];
    bf16* Qh  = (bf16*)smraw;               // 256 x QS_STR
    bf16* Ql  = Qh + 256 * QS_STR;
    bf16* Kh  = Ql + 256 * QS_STR;          // 256 x KS_STR
    bf16* Kl  = Kh + 256 * KS_STR;
    bf16* Vth = Kl + 256 * KS_STR;          // 32 x VT_STR  [c][k]
    bf16* Vtl = Vth + 32 * VT_STR;

    const int tid = threadIdx.x;
    const int wid = tid >> 5, lane = tid & 31;
    const int lr  = lane >> 2, lc = lane & 3;
    const int h   = blockIdx.x;             // 0..3
    const int i   = blockIdx.y;             // 0..255
    const int i_row0 = i * NSEQ;

    // ---- stage Q,K via cp.async; V transposed manually (overlapped) ----
    #pragma unroll
    for (int it = 0; it < 4; ++it) {
        int idx = tid + it * 256;
        int j = idx >> 2, cq = idx & 3;
        size_t src = (size_t)(i_row0 + j) * 384 + h * 32 + cq * 8;
        uint32_t dq = smaddr(&Qh[j * QS_STR + cq * 8]);
        CP_ASYNC16(dq, g_qkvh + src);
        CP_ASYNC16(dq + 256 * QS_STR * 2, g_qkvl + src);
        uint32_t dk = smaddr(&Kh[j * KS_STR + cq * 8]);
        CP_ASYNC16(dk, g_qkvh + src + 128);
        CP_ASYNC16(dk + 256 * KS_STR * 2, g_qkvl + src + 128);
    }
    CP_COMMIT();
    #pragma unroll
    for (int it = 0; it < 4; ++it) {
        int idx = tid + it * 256;
        int k = idx >> 2, cq = idx & 3;
        size_t src = (size_t)(i_row0 + k) * 384 + h * 32 + cq * 8 + 256;
        uint4 vh = *(const uint4*)(g_qkvh + src);
        uint4 vl = *(const uint4*)(g_qkvl + src);
        bf16 th[8], tl[8];
        *(uint4*)th = vh; *(uint4*)tl = vl;
        #pragma unroll
        for (int e = 0; e < 8; ++e) {
            Vth[(cq * 8 + e) * VT_STR + k] = th[e];
            Vtl[(cq * 8 + e) * VT_STR + k] = tl[e];
        }
    }
    CP_WAIT(0);
    __syncthreads();

    // ---- resident Q fragments for both m-tiles ----
    uint32_t qfh[2][2][4], qfl[2][2][4];
    #pragma unroll
    for (int mt = 0; mt < 2; ++mt) {
        int r = wid * 32 + mt * 16 + lr;
        #pragma unroll
        for (int kt = 0; kt < 2; ++kt) {
            int c = kt * 16 + lc * 2;
            qfh[mt][kt][0] = *(const uint32_t*)&Qh[ r      * QS_STR + c];
            qfh[mt][kt][1] = *(const uint32_t*)&Qh[(r + 8) * QS_STR + c];
            qfh[mt][kt][2] = *(const uint32_t*)&Qh[ r      * QS_STR + c + 8];
            qfh[mt][kt][3] = *(const uint32_t*)&Qh[(r + 8) * QS_STR + c + 8];
            qfl[mt][kt][0] = *(const uint32_t*)&Ql[ r      * QS_STR + c];
            qfl[mt][kt][1] = *(const uint32_t*)&Ql[(r + 8) * QS_STR + c];
            qfl[mt][kt][2] = *(const uint32_t*)&Ql[ r      * QS_STR + c + 8];
            qfl[mt][kt][3] = *(const uint32_t*)&Ql[(r + 8) * QS_STR + c + 8];
        }
    }

    const float scaleL = 0.17677669529663687f * LOG2E;
    float mrow[2][2], srow[2][2];
    #pragma unroll
    for (int mt = 0; mt < 2; ++mt) {
        mrow[mt][0] = mrow[mt][1] = -1e30f;
        srow[mt][0] = srow[mt][1] = 0.0f;
    }
    float oacc[2][4][4];
    #pragma unroll
    for (int mt = 0; mt < 2; ++mt)
        #pragma unroll
        for (int cn = 0; cn < 4; ++cn)
            #pragma unroll
            for (int e = 0; e < 4; ++e) oacc[mt][cn][e] = 0.0f;

    for (int q = 0; q < 4; ++q) {
        const int k0 = q * 64;
        float acc[2][8][4];
        #pragma unroll
        for (int mt = 0; mt < 2; ++mt)
            #pragma unroll
            for (int nt = 0; nt < 8; ++nt)
                #pragma unroll
                for (int e = 0; e < 4; ++e) acc[mt][nt][e] = 0.0f;

        // ---- scores for 32 rows x 64 k: B-frag loaded once, 6 MMAs ----
        #pragma unroll
        for (int nt = 0; nt < 8; ++nt) {
            int n = k0 + nt * 8 + lr;
            #pragma unroll
            for (int kt = 0; kt < 2; ++kt) {
                int c = kt * 16 + lc * 2;
                uint32_t bh0 = *(const uint32_t*)&Kh[n * KS_STR + c];
                uint32_t bh1 = *(const uint32_t*)&Kh[n * KS_STR + c + 8];
                uint32_t bl0 = *(const uint32_t*)&Kl[n * KS_STR + c];
                uint32_t bl1 = *(const uint32_t*)&Kl[n * KS_STR + c + 8];
                #pragma unroll
                for (int mt = 0; mt < 2; ++mt) {
                    MMA16816(acc[mt][nt], qfh[mt][kt], bh0, bh1);
                    MMA16816(acc[mt][nt], qfh[mt][kt], bl0, bl1);
                    MMA16816(acc[mt][nt], qfl[mt][kt], bh0, bh1);
                }
            }
        }

        // ---- online softmax update per m-tile ----
        #pragma unroll
        for (int mt = 0; mt < 2; ++mt) {
            int jg1 = wid * 32 + mt * 16 + lr;
            const float* brow1 = g_bias + (size_t)h * NROWS + (size_t)jg1 * NSEQ;
            const float* brow2 = brow1 + 8 * NSEQ;
            float lmx1 = -1e30f, lmx2 = -1e30f;
            #pragma unroll
            for (int nt = 0; nt < 8; ++nt) {
                int col = k0 + nt * 8 + lc * 2;
                float2 b1 = *(const float2*)(brow1 + col);
                float2 b2 = *(const float2*)(brow2 + col);
                acc[mt][nt][0] = acc[mt][nt][0] * scaleL + b1.x;
                acc[mt][nt][1] = acc[mt][nt][1] * scaleL + b1.y;
                acc[mt][nt][2] = acc[mt][nt][2] * scaleL + b2.x;
                acc[mt][nt][3] = acc[mt][nt][3] * scaleL + b2.y;
                lmx1 = fmaxf(lmx1, fmaxf(acc[mt][nt][0], acc[mt][nt][1]));
                lmx2 = fmaxf(lmx2, fmaxf(acc[mt][nt][2], acc[mt][nt][3]));
            }
            lmx1 = fmaxf(lmx1, __shfl_xor_sync(0xffffffffu, lmx1, 1));
            lmx1 = fmaxf(lmx1, __shfl_xor_sync(0xffffffffu, lmx1, 2));
            lmx2 = fmaxf(lmx2, __shfl_xor_sync(0xffffffffu, lmx2, 1));
            lmx2 = fmaxf(lmx2, __shfl_xor_sync(0xffffffffu, lmx2, 2));

            float m1n = fmaxf(mrow[mt][0], lmx1);
            float m2n = fmaxf(mrow[mt][1], lmx2);
            float f1 = ex2(mrow[mt][0] - m1n);
            float f2 = ex2(mrow[mt][1] - m2n);
            float ls1 = 0.0f, ls2 = 0.0f;
            #pragma unroll
            for (int nt = 0; nt < 8; ++nt) {
                acc[mt][nt][0] = ex2(acc[mt][nt][0] - m1n);
                acc[mt][nt][1] = ex2(acc[mt][nt][1] - m1n);
                acc[mt][nt][2] = ex2(acc[mt][nt][2] - m2n);
                acc[mt][nt][3] = ex2(acc[mt][nt][3] - m2n);
                ls1 += acc[mt][nt][0] + acc[mt][nt][1];
                ls2 += acc[mt][nt][2] + acc[mt][nt][3];
            }
            ls1 += __shfl_xor_sync(0xffffffffu, ls1, 1);
            ls1 += __shfl_xor_sync(0xffffffffu, ls1, 2);
            ls2 += __shfl_xor_sync(0xffffffffu, ls2, 1);
            ls2 += __shfl_xor_sync(0xffffffffu, ls2, 2);
            srow[mt][0] = srow[mt][0] * f1 + ls1;
            srow[mt][1] = srow[mt][1] * f2 + ls2;
            mrow[mt][0] = m1n; mrow[mt][1] = m2n;

            #pragma unroll
            for (int cn = 0; cn < 4; ++cn) {
                oacc[mt][cn][0] *= f1; oacc[mt][cn][1] *= f1;
                oacc[mt][cn][2] *= f2; oacc[mt][cn][3] *= f2;
            }
        }

        // ---- P V for this quarter: V-frag loaded once, 6 MMAs ----
        #pragma unroll
        for (int kt = 0; kt < 4; ++kt) {
            int nt0 = 2 * kt, nt1 = 2 * kt + 1;
            uint32_t ah[2][4], al[2][4];
            #pragma unroll
            for (int mt = 0; mt < 2; ++mt) {
                __nv_bfloat162 hh, ll;
                hh = __floats2bfloat162_rn(acc[mt][nt0][0], acc[mt][nt0][1]);
                ll = __floats2bfloat162_rn(acc[mt][nt0][0] - __bfloat162float(hh.x),
                                           acc[mt][nt0][1] - __bfloat162float(hh.y));
                ah[mt][0] = *(uint32_t*)&hh; al[mt][0] = *(uint32_t*)&ll;
                hh = __floats2bfloat162_rn(acc[mt][nt0][2], acc[mt][nt0][3]);
                ll = __floats2bfloat162_rn(acc[mt][nt0][2] - __bfloat162float(hh.x),
                                           acc[mt][nt0][3] - __bfloat162float(hh.y));
                ah[mt][1] = *(uint32_t*)&hh; al[mt][1] = *(uint32_t*)&ll;
                hh = __floats2bfloat162_rn(acc[mt][nt1][0], acc[mt][nt1][1]);
                ll = __floats2bfloat162_rn(acc[mt][nt1][0] - __bfloat162float(hh.x),
                                           acc[mt][nt1][1] - __bfloat162float(hh.y));
                ah[mt][2] = *(uint32_t*)&hh; al[mt][2] = *(uint32_t*)&ll;
                hh = __floats2bfloat162_rn(acc[mt][nt1][2], acc[mt][nt1][3]);
                ll = __floats2bfloat162_rn(acc[mt][nt1][2] - __bfloat162float(hh.x),
                                           acc[mt][nt1][3] - __bfloat162float(hh.y));
                ah[mt][3] = *(uint32_t*)&hh; al[mt][3] = *(uint32_t*)&ll;
            }
            int kb = k0 + kt * 16;
            #pragma unroll
            for (int cn = 0; cn < 4; ++cn) {
                int c = cn * 8 + lr;
                uint32_t bh0 = *(const uint32_t*)&Vth[c * VT_STR + kb + lc * 2];
                uint32_t bh1 = *(const uint32_t*)&Vth[c * VT_STR + kb + 8 + lc * 2];
                uint32_t bl0 = *(const uint32_t*)&Vtl[c * VT_STR + kb + lc * 2];
                uint32_t bl1 = *(const uint32_t*)&Vtl[c * VT_STR + kb + 8 + lc * 2];
                #pragma unroll
                for (int mt = 0; mt < 2; ++mt) {
                    MMA16816(oacc[mt][cn], ah[mt], bh0, bh1);
                    MMA16816(oacc[mt][cn], ah[mt], bl0, bl1);
                    MMA16816(oacc[mt][cn], al[mt], bh0, bh1);
                }
            }
        }
    }

    // ---- normalize, gate, split-store (warp-local) ----
    #pragma unroll
    for (int mt = 0; mt < 2; ++mt) {
        float inv1 = 1.0f / srow[mt][0], inv2 = 1.0f / srow[mt][1];
        int jg1 = wid * 32 + mt * 16 + lr;
        size_t row1 = (size_t)(i_row0 + jg1) * 128 + h * 32;
        size_t row2 = row1 + (size_t)8 * 128;
        #pragma unroll
        for (int cn = 0; cn < 4; ++cn) {
            int c = cn * 8 + lc * 2;
            float2 g1 = *(const float2*)(g_gate + row1 + c);
            float2 g2 = *(const float2*)(g_gate + row2 + c);
            float x0 = oacc[mt][cn][0] * inv1 * g1.x;
            float x1 = oacc[mt][cn][1] * inv1 * g1.y;
            float x2 = oacc[mt][cn][2] * inv2 * g2.x;
            float x3 = oacc[mt][cn][3] * inv2 * g2.y;
            __nv_bfloat162 h1 = __floats2bfloat162_rn(x0, x1);
            __nv_bfloat162 l1 = __floats2bfloat162_rn(x0 - __bfloat162float(h1.x),
                                                      x1 - __bfloat162float(h1.y));
            __nv_bfloat162 h2 = __floats2bfloat162_rn(x2, x3);
            __nv_bfloat162 l2 = __floats2bfloat162_rn(x2 - __bfloat162float(h2.x),
                                                      x3 - __bfloat162float(h2.y));
            *(__nv_bfloat162*)(g_go_h + row1 + c) = h1;
            *(__nv_bfloat162*)(g_go_l + row1 + c) = l1;
            *(__nv_bfloat162*)(g_go_h + row2 + c) = h2;
            *(__nv_bfloat162*)(g_go_l + row2 + c) = l2;
        }
    }
}

// ---------------- launch ----------------
extern "C" void kernel_launch(void* const* d_in, const int* in_sizes, int n_in,
                              void* d_out, int out_size)
{
    const float* z    = (const float*)d_in[0];
    const float* ln_g = (const float*)d_in[1];
    const float* ln_b = (const float*)d_in[2];
    const float* Wqkv = (const float*)d_in[3];
    const float* Wb   = (const float*)d_in[4];
    const float* Wg   = (const float*)d_in[5];
    const float* Wo   = (const float*)d_in[6];
    float* out = (float*)d_out;

    cudaFuncSetAttribute(attn_kernel, cudaFuncAttributeMaxDynamicSharedMemorySize, ATTN_SMEM);
    cudaFuncSetAttribute(mma_gemm, cudaFuncAttributeMaxDynamicSharedMemorySize, GEMM_SMEM);

    void *pznh, *pznl, *pqh, *pql, *pgate, *pgoh, *pgol;
    void *pwch, *pwcl, *pwoh, *pwol;
    cudaGetSymbolAddress(&pznh, g_zn_h);
    cudaGetSymbolAddress(&pznl, g_zn_l);
    cudaGetSymbolAddress(&pqh,  g_qkvh);
    cudaGetSymbolAddress(&pql,  g_qkvl);
    cudaGetSymbolAddress(&pgate, g_gate);
    cudaGetSymbolAddress(&pgoh, g_go_h);
    cudaGetSymbolAddress(&pgol, g_go_l);
    cudaGetSymbolAddress(&pwch, g_wcat_h);
    cudaGetSymbolAddress(&pwcl, g_wcat_l);
    cudaGetSymbolAddress(&pwoh, g_wo_h);
    cudaGetSymbolAddress(&pwol, g_wo_l);

    ln_kernel<<<NROWS / 8, 256>>>(z, ln_g, ln_b, Wb);
    cvt_w<<<320, 256>>>(Wqkv, Wg, Wo);
    // fused: qkv (split bf16) + gate (sigmoid f32) from combined weight
    mma_gemm<<<dim3(NROWS / 128, 4), 256, GEMM_SMEM>>>(
        (const bf16*)pznh, (const bf16*)pznl,
        (const bf16*)pwch, (const bf16*)pwcl,
        (float*)pgate, (bf16*)pqh, (bf16*)pql, 512, 3);
    attn_kernel<<<dim3(NHEAD, NSEQ), 256, ATTN_SMEM>>>();
    // out = (gate*o) @ Wo -> f32
    mma_gemm<<<dim3(NROWS / 128, 1), 256, GEMM_SMEM>>>(
        (const bf16*)pgoh, (const bf16*)pgol,
        (const bf16*)pwoh, (const bf16*)pwol,
        out, nullptr, nullptr, 128, 0);
}